// round 16
// baseline (speedup 1.0000x reference)
#include <cuda_runtime.h>
#include <cuda_bf16.h>
#include <math.h>
#include <stdint.h>

#define CH 384
#define RR 32
#define S 32768             // 32^3
#define BATCH 2
#define KPRIME 1152         // 3*384 bf16x3 folded K
#define NSTAGE 18           // KPRIME / 64
#define NPIPE 3             // cp.async pipeline depth
#define AP_ELE (CH * KPRIME)
#define NTHR 256            // 8 warps per CTA

// smem geometry (bytes)
#define A_STRIDE 144        // (64+8) bf16 per row
#define B_STRIDE 272        // (128+8) bf16 per row
#define A_BYTES  (128 * A_STRIDE)   // 18432
#define B_BYTES  (64 * B_STRIDE)    // 17408
#define STAGE_BYTES (A_BYTES + B_BYTES)  // 35840
#define SMEM_GEMM (NPIPE * STAGE_BYTES)  // 107520

// ---------------- scratch (__device__ globals; alloc-free rule) ----------------
__device__ __align__(16) float    g_buf[BATCH * CH * S];            // fp32 activations
__device__ __align__(16) unsigned short g_hi1[BATCH * CH * S];      // plane set 1 (x, then gelu(gn1))
__device__ __align__(16) unsigned short g_lo1[BATCH * CH * S];
__device__ __align__(16) unsigned short g_hi2[BATCH * CH * S];      // plane set 2 (gn2 input)
__device__ __align__(16) unsigned short g_lo2[BATCH * CH * S];
__device__ __align__(16) unsigned short g_apack[5 * AP_ELE];        // packed bf16x3 weights
__device__ float g_acc1[2 * BATCH];     // GN1 (sum, sumsq) atomics
__device__ float g_acc2[2 * BATCH];     // GN2 (sum, sumsq) atomics
__device__ float g_stats1[2 * BATCH];   // GN1 (mean, rstd)
__device__ float g_stats2[2 * BATCH];   // GN2 (mean, rstd)
__device__ float g_cvec[CH];            // b3 + w3·bt2
__device__ float g_wrsum[CH];           // rowsum(w3·g2)

__device__ __forceinline__ float gelu_f(float x) {
    return 0.5f * x * (1.0f + erff(x * 0.70710678118654752f));
}

// ---------------- PTX helpers (compute_80-compatible) ----------------
__device__ __forceinline__ uint32_t smem_u32(const void* p) {
    uint32_t a;
    asm("{ .reg .u64 t; cvta.to.shared.u64 t, %1; cvt.u32.u64 %0, t; }" : "=r"(a) : "l"(p));
    return a;
}
__device__ __forceinline__ void cp16(uint32_t dst, const void* src) {
    asm volatile("cp.async.cg.shared.global [%0], [%1], 16;" :: "r"(dst), "l"(src));
}
// ignore-src form: src_size=0 -> hardware zero-fill (boundary handling)
__device__ __forceinline__ void cp16z(uint32_t dst, const void* src, bool pred) {
    const int sz = pred ? 16 : 0;
    asm volatile("cp.async.cg.shared.global [%0], [%1], 16, %2;"
                 :: "r"(dst), "l"(src), "r"(sz));
}
__device__ __forceinline__ void ldsm4(uint32_t* r, uint32_t addr) {
    asm volatile("ldmatrix.sync.aligned.m8n8.x4.shared.b16 {%0,%1,%2,%3}, [%4];"
        : "=r"(r[0]), "=r"(r[1]), "=r"(r[2]), "=r"(r[3]) : "r"(addr));
}
__device__ __forceinline__ void ldsm4t(uint32_t* r, uint32_t addr) {
    asm volatile("ldmatrix.sync.aligned.m8n8.x4.trans.shared.b16 {%0,%1,%2,%3}, [%4];"
        : "=r"(r[0]), "=r"(r[1]), "=r"(r[2]), "=r"(r[3]) : "r"(addr));
}
__device__ __forceinline__ void mma16816(float* c, const uint32_t* a, uint32_t b0, uint32_t b1) {
    asm volatile("mma.sync.aligned.m16n8k16.row.col.f32.bf16.bf16.f32 "
        "{%0,%1,%2,%3}, {%4,%5,%6,%7}, {%8,%9}, {%0,%1,%2,%3};"
        : "+f"(c[0]), "+f"(c[1]), "+f"(c[2]), "+f"(c[3])
        : "r"(a[0]), "r"(a[1]), "r"(a[2]), "r"(a[3]), "r"(b0), "r"(b1));
}
__device__ __forceinline__ void split_one(float v, unsigned short& hi, unsigned short& lo) {
    const __nv_bfloat16 h = __float2bfloat16_rn(v);
    const __nv_bfloat16 l = __float2bfloat16_rn(v - __bfloat162float(h));
    hi = __bfloat16_as_ushort(h);
    lo = __bfloat16_as_ushort(l);
}

// =====================================================================
// HMMA bf16x3 GEMM, 8 warps x (64x32) warp tiles. modes:
//  0: write fp32 acc+bias; fused GN1 stats -> accOut
//  1: write gelu(acc+bias) fp32
//  2: Out += gelu(acc+bias) fp32
//  3: v = Out + gelu(acc+bias); fused GN2 stats -> accOut; write hi/lo set2
//  4: final: v = rstd*acc + (bias[m] - rstd*mean*wrsum[m]); write fp32 Out
// axis: <0 dense; 2/3 = d/h shift via cp.async zero-fill; 4 = w shift via shfl
// =====================================================================
__device__ __forceinline__ void load_stage(
    char* smem, uint32_t sb, int c, int tid, int b, int m0, int n0, int axis,
    const unsigned short* __restrict__ apack,
    const unsigned short* __restrict__ hiP,
    const unsigned short* __restrict__ loP)
{
    const uint32_t stOff = (uint32_t)(c % NPIPE) * STAGE_BYTES;
    const uint32_t aBase = sb + stOff;
    const uint32_t bBase = aBase + A_BYTES;
    // ---- A: 128 rows x 64 bf16 (cp.async 16B) ----
    const unsigned short* ag = apack + (long)m0 * KPRIME + c * 64;
    #pragma unroll
    for (int it = 0; it < 4; it++) {
        const int flat = it * NTHR + tid;   // 0..1023
        const int m = flat >> 3, g = flat & 7;
        cp16(aBase + m * A_STRIDE + g * 16, ag + (long)m * KPRIME + g * 8);
    }
    const int kbase = (c % 6) * 64;
    const unsigned short* plane = (c < 12) ? hiP : loP;
    if (axis < 0) {
        // ---- dense B: 64 rows x 16 cp16 ----
        #pragma unroll
        for (int it = 0; it < 4; it++) {
            const int flat = it * NTHR + tid;   // 0..1023
            const int k = flat >> 4, g = flat & 15;
            cp16(bBase + k * B_STRIDE + g * 16,
                 plane + ((long)b * CH + kbase + k) * (long)S + n0 + g * 8);
        }
    } else if (axis == 2 || axis == 3) {
        // ---- d/h shift: 16B alignment preserved -> cp.async with zero-fill ----
        #pragma unroll
        for (int it = 0; it < 4; it++) {
            const int flat = it * NTHR + tid;   // 0..1023
            const int k = flat >> 4, g = flat & 15;
            const int ch = kbase + k;
            const int n = n0 + g * 8;
            int d = n >> 10, h = (n >> 5) & 31;
            const int w = n & 31;
            const int delta = 1 - (ch >> 7);    // {+1, 0, -1}
            int coord;
            if (axis == 2) { d += delta; coord = d; }
            else           { h += delta; coord = h; }
            const unsigned short* src = plane + (((long)b * CH + ch) << 15)
                                      + (d << 10) + (h << 5) + w;
            cp16z(bBase + k * B_STRIDE + g * 16, src, (unsigned)coord < 32u);
        }
    } else {
        // ---- w shift: aligned u32 load + warp shuffle funnel (delta warp-uniform) ----
        #pragma unroll
        for (int it = 0; it < 16; it++) {
            const int flat = it * NTHR + tid;   // 0..4095
            const int k = flat >> 6, ni2 = flat & 63;
            const int ch = kbase + k;
            const int delta = 1 - (ch >> 7);
            const long base32 = (((long)b * CH + ch) << 14) + (n0 >> 1);
            const uint32_t u = reinterpret_cast<const uint32_t*>(plane)[base32 + ni2];
            const int wp = ni2 & 15;            // w-pair index within h-row
            uint32_t v;
            if (delta == 0) {
                v = u;
            } else if (delta > 0) {             // x[w] = h[w+1]
                uint32_t nx = __shfl_down_sync(0xFFFFFFFFu, u, 1);
                if (wp == 15) nx = 0;           // h[32] -> 0
                v = (u >> 16) | (nx << 16);
            } else {                            // x[w] = h[w-1]
                uint32_t pv = __shfl_up_sync(0xFFFFFFFFu, u, 1);
                if (wp == 0) pv = 0;            // h[-1] -> 0
                v = (u << 16) | (pv >> 16);
            }
            *reinterpret_cast<uint32_t*>(smem + stOff + A_BYTES + k * B_STRIDE + ni2 * 4) = v;
        }
    }
    asm volatile("cp.async.commit_group;" ::: "memory");
}

__global__ __launch_bounds__(NTHR, 2)
void gemm_tc(const unsigned short* __restrict__ apack,
             const unsigned short* __restrict__ hiP,
             const unsigned short* __restrict__ loP,
             float* __restrict__ Out, const float* __restrict__ bias,
             int axis, int mode,
             float* __restrict__ accOut,
             unsigned short* __restrict__ outHi, unsigned short* __restrict__ outLo,
             const float* __restrict__ stats2, const float* __restrict__ wrsum)
{
    extern __shared__ char smem[];
    const uint32_t sb = smem_u32(smem);
    const int tid = threadIdx.x, wid = tid >> 5, lane = tid & 31;
    const int m0 = blockIdx.x * 128;
    const int n0 = blockIdx.y * 128;
    const int b  = blockIdx.z;
    const int wm = (wid & 1) * 64;
    const int wn = (wid >> 1) * 32;

    float acc[4][4][4];
    #pragma unroll
    for (int i = 0; i < 4; i++)
        #pragma unroll
        for (int j = 0; j < 4; j++)
            #pragma unroll
            for (int k = 0; k < 4; k++) acc[i][j][k] = 0.f;

    load_stage(smem, sb, 0, tid, b, m0, n0, axis, apack, hiP, loP);
    load_stage(smem, sb, 1, tid, b, m0, n0, axis, apack, hiP, loP);

    for (int c = 0; c < NSTAGE; c++) {
        if (c < NSTAGE - 1)
            asm volatile("cp.async.wait_group 1;" ::: "memory");
        else
            asm volatile("cp.async.wait_group 0;" ::: "memory");
        __syncthreads();

        // prefetch stage c+2 first (slot (c+2)%3 == (c-1)%3, free after barrier)
        if (c + 2 < NSTAGE)
            load_stage(smem, sb, c + 2, tid, b, m0, n0, axis, apack, hiP, loP);

        const uint32_t aBase = sb + (uint32_t)(c % NPIPE) * STAGE_BYTES;
        const uint32_t bBase = aBase + A_BYTES;
        #pragma unroll
        for (int ks = 0; ks < 4; ks++) {
            const int k0 = ks * 16;
            uint32_t afr[4][4], bfr[2][4];
            #pragma unroll
            for (int mt = 0; mt < 4; mt++)
                ldsm4(afr[mt], aBase + (wm + mt * 16 + (lane & 15)) * A_STRIDE
                               + (k0 + (lane >> 4) * 8) * 2);
            #pragma unroll
            for (int nt = 0; nt < 2; nt++)
                ldsm4t(bfr[nt], bBase + (k0 + (lane & 15)) * B_STRIDE
                                + (wn + nt * 16 + (lane >> 4) * 8) * 2);
            #pragma unroll
            for (int mt = 0; mt < 4; mt++)
                #pragma unroll
                for (int n8 = 0; n8 < 4; n8++)
                    mma16816(acc[mt][n8], afr[mt],
                             bfr[n8 >> 1][(n8 & 1) * 2],
                             bfr[n8 >> 1][(n8 & 1) * 2 + 1]);
        }
    }

    // ---- epilogue ----
    float mean = 0.f, rstd = 1.f;
    if (mode == 4) { mean = stats2[2 * b]; rstd = stats2[2 * b + 1]; }
    float ls = 0.f, lss = 0.f;
    const int g = lane >> 2, t = lane & 3;
    #pragma unroll
    for (int mt = 0; mt < 4; mt++) {
        #pragma unroll
        for (int half = 0; half < 2; half++) {
            const int m = m0 + wm + mt * 16 + g + half * 8;
            const float bv = bias[m];
            float cc = bv;
            if (mode == 4) cc = bv - rstd * mean * wrsum[m];
            const long rowbase = ((long)b * CH + m) * (long)S + n0 + wn;
            float* op = Out + rowbase;
            #pragma unroll
            for (int n8 = 0; n8 < 4; n8++) {
                float2 v;
                if (mode == 4) {
                    v.x = rstd * acc[mt][n8][half * 2]     + cc;
                    v.y = rstd * acc[mt][n8][half * 2 + 1] + cc;
                } else {
                    v.x = acc[mt][n8][half * 2]     + bv;
                    v.y = acc[mt][n8][half * 2 + 1] + bv;
                }
                if (mode == 1 || mode == 2 || mode == 3) {
                    v.x = gelu_f(v.x); v.y = gelu_f(v.y);
                }
                const int nofs = n8 * 8 + 2 * t;
                if (mode == 2 || mode == 3) {
                    float2 o = *reinterpret_cast<const float2*>(op + nofs);
                    v.x += o.x; v.y += o.y;
                }
                if (mode == 0) {
                    ls += v.x + v.y;
                    lss = fmaf(v.x, v.x, lss); lss = fmaf(v.y, v.y, lss);
                }
                if (mode == 3) {
                    ls += v.x + v.y;
                    lss = fmaf(v.x, v.x, lss); lss = fmaf(v.y, v.y, lss);
                    unsigned short hx, lx, hy, ly;
                    split_one(v.x, hx, lx); split_one(v.y, hy, ly);
                    const long u32i = (rowbase + nofs) >> 1;
                    reinterpret_cast<uint32_t*>(outHi)[u32i] = (uint32_t)hx | ((uint32_t)hy << 16);
                    reinterpret_cast<uint32_t*>(outLo)[u32i] = (uint32_t)lx | ((uint32_t)ly << 16);
                } else {
                    *reinterpret_cast<float2*>(op + nofs) = v;
                }
            }
        }
    }
    // ---- fused stats reduction ----
    if (mode == 0 || mode == 3) {
        #pragma unroll
        for (int off = 16; off; off >>= 1) {
            ls  += __shfl_xor_sync(0xFFFFFFFFu, ls,  off);
            lss += __shfl_xor_sync(0xFFFFFFFFu, lss, off);
        }
        float* sred = reinterpret_cast<float*>(smem);
        __syncthreads();
        if (lane == 0) { sred[wid] = ls; sred[8 + wid] = lss; }
        __syncthreads();
        if (tid == 0) {
            float s = 0.f, ss = 0.f;
            #pragma unroll
            for (int i = 0; i < 8; i++) { s += sred[i]; ss += sred[8 + i]; }
            atomicAdd(&accOut[2 * b],     s);
            atomicAdd(&accOut[2 * b + 1], ss);
        }
    }
}

// ============ zero stats accumulators ============
__global__ void zero_acc()
{
    if (threadIdx.x < 2 * BATCH) { g_acc1[threadIdx.x] = 0.f; g_acc2[threadIdx.x] = 0.f; }
}

// ============ finalize stats: (sum,sumsq) -> (mean, rstd) ============
__global__ void finalize_stats(const float* __restrict__ acc, float* __restrict__ stats)
{
    const int b = threadIdx.x;
    if (b >= BATCH) return;
    const float n = (float)CH * (float)S;
    const float mean = acc[2 * b] / n;
    const float var  = acc[2 * b + 1] / n - mean * mean;
    stats[2 * b]     = mean;
    stats[2 * b + 1] = rsqrtf(var + 1e-5f);
}

// ============ pack weights: [mat][m][ hi(384) | lo(384) | hi(384) ] ============
__global__ void apack_prep(const float* __restrict__ w1, const float* __restrict__ w21,
                           const float* __restrict__ w22, const float* __restrict__ w23,
                           const float* __restrict__ w3, const float* __restrict__ g2)
{
    const int idx = blockIdx.x * blockDim.x + threadIdx.x;
    if (idx >= 5 * CH * CH) return;
    const int mat = idx / (CH * CH);
    const int rem = idx % (CH * CH);
    const int m = rem / CH, k = rem % CH;
    const float* W = (mat == 0) ? w1 : (mat == 1) ? w21 : (mat == 2) ? w22
                   : (mat == 3) ? w23 : w3;
    float v = W[m * CH + k];
    if (mat == 4) v *= g2[k];
    unsigned short hi, lo;
    split_one(v, hi, lo);
    const long base = (long)mat * AP_ELE + (long)m * KPRIME;
    g_apack[base + k]           = hi;
    g_apack[base + CH + k]      = lo;
    g_apack[base + 2 * CH + k]  = hi;
}

// ============ convert raw x -> plane set 1 ============
__global__ void convert_x(const float* __restrict__ x)
{
    const long i = (long)blockIdx.x * blockDim.x + threadIdx.x;
    const long tot2 = (long)BATCH * CH * S / 2;
    if (i >= tot2) return;
    const float2 v = reinterpret_cast<const float2*>(x)[i];
    unsigned short h0, l0, h1, l1;
    split_one(v.x, h0, l0); split_one(v.y, h1, l1);
    reinterpret_cast<uint32_t*>(g_hi1)[i] = (uint32_t)h0 | ((uint32_t)h1 << 16);
    reinterpret_cast<uint32_t*>(g_lo1)[i] = (uint32_t)l0 | ((uint32_t)l1 << 16);
}

// ============ GN1 affine + GELU -> plane set 1 (dense, overwrites x planes) ======
__global__ void gn1_split(const float* __restrict__ g1, const float* __restrict__ bt1)
{
    const long i = (long)blockIdx.x * blockDim.x + threadIdx.x;
    const long tot2 = (long)BATCH * CH * S / 2;
    if (i >= tot2) return;
    const int b = (int)(i / ((long)CH * (S / 2)));
    const int c = (int)((i >> 14) % CH);          // S/2 = 16384 pairs per channel
    const float rstd = g_stats1[2 * b + 1];
    const float ga = rstd * g1[c];
    const float bb = bt1[c] - g_stats1[2 * b] * ga;
    const float2 v = reinterpret_cast<const float2*>(g_buf)[i];
    const float y0 = gelu_f(fmaf(v.x, ga, bb));
    const float y1 = gelu_f(fmaf(v.y, ga, bb));
    unsigned short h0, l0, h1, l1;
    split_one(y0, h0, l0); split_one(y1, h1, l1);
    reinterpret_cast<uint32_t*>(g_hi1)[i] = (uint32_t)h0 | ((uint32_t)h1 << 16);
    reinterpret_cast<uint32_t*>(g_lo1)[i] = (uint32_t)l0 | ((uint32_t)l1 << 16);
}

// ====== cvec[o] = b3[o] + w3[o,:]·bt2 ; wrsum[o] = (w3·g2)[o,:]·1 ======
__global__ void cvec_kernel(const float* __restrict__ w3,
                            const float* __restrict__ bt2,
                            const float* __restrict__ b3,
                            const float* __restrict__ g2)
{
    const int o = blockIdx.x * blockDim.x + threadIdx.x;
    if (o >= CH) return;
    float s = b3[o], ws = 0.f;
    for (int c = 0; c < CH; c++) {
        s  = fmaf(w3[o * CH + c], bt2[c], s);
        ws = fmaf(w3[o * CH + c], g2[c], ws);
    }
    g_cvec[o]  = s;
    g_wrsum[o] = ws;
}

extern "C" void kernel_launch(void* const* d_in, const int* in_sizes, int n_in,
                              void* d_out, int out_size)
{
    const float* x   = (const float*)d_in[0];
    const float* w1  = (const float*)d_in[1];
    const float* b1  = (const float*)d_in[2];
    const float* g1  = (const float*)d_in[3];
    const float* bt1 = (const float*)d_in[4];
    const float* w21 = (const float*)d_in[5];
    const float* b21 = (const float*)d_in[6];
    const float* w22 = (const float*)d_in[7];
    const float* b22 = (const float*)d_in[8];
    const float* w23 = (const float*)d_in[9];
    const float* b23 = (const float*)d_in[10];
    const float* g2  = (const float*)d_in[11];
    const float* bt2 = (const float*)d_in[12];
    const float* w3  = (const float*)d_in[13];
    const float* b3  = (const float*)d_in[14];
    float* out = (float*)d_out;

    float*          buf;   cudaGetSymbolAddress((void**)&buf,   g_buf);
    unsigned short* hi1;   cudaGetSymbolAddress((void**)&hi1,   g_hi1);
    unsigned short* lo1;   cudaGetSymbolAddress((void**)&lo1,   g_lo1);
    unsigned short* hi2;   cudaGetSymbolAddress((void**)&hi2,   g_hi2);
    unsigned short* lo2;   cudaGetSymbolAddress((void**)&lo2,   g_lo2);
    unsigned short* apk;   cudaGetSymbolAddress((void**)&apk,   g_apack);
    float*          cvec;  cudaGetSymbolAddress((void**)&cvec,  g_cvec);
    float*          wrs;   cudaGetSymbolAddress((void**)&wrs,   g_wrsum);
    float*          acc1;  cudaGetSymbolAddress((void**)&acc1,  g_acc1);
    float*          acc2;  cudaGetSymbolAddress((void**)&acc2,  g_acc2);
    float*          st1;   cudaGetSymbolAddress((void**)&st1,   g_stats1);
    float*          st2;   cudaGetSymbolAddress((void**)&st2,   g_stats2);

    cudaFuncSetAttribute(gemm_tc, cudaFuncAttributeMaxDynamicSharedMemorySize, SMEM_GEMM);

    const dim3 gg(3, S / 128, BATCH);   // m fastest -> L2 reuse of B across m-tiles
    const long tot2 = (long)BATCH * CH * S / 2;
    const unsigned ew = (unsigned)((tot2 + 255) / 256);

    // 0) zero accumulators; pack weights; fold biases; convert x
    zero_acc<<<1, 32>>>();
    apack_prep<<<(5 * CH * CH + 255) / 256, 256>>>(w1, w21, w22, w23, w3, g2);
    cvec_kernel<<<2, 192>>>(w3, bt2, b3, g2);
    convert_x<<<ew, 256>>>(x);
    // 1) conv1 (mode 0: + fused GN1 stats)
    gemm_tc<<<gg, NTHR, SMEM_GEMM>>>(apk + 0L * AP_ELE, hi1, lo1, buf, b1, -1, 0,
                                     acc1, nullptr, nullptr, nullptr, nullptr);
    finalize_stats<<<1, 32>>>(acc1, st1);
    // 2) GN1 affine + GELU -> plane set 1 (dense)
    gn1_split<<<ew, 256>>>(g1, bt1);
    // 3) three shifted branch convs; last fuses GN2 stats + plane-set-2 write
    gemm_tc<<<gg, NTHR, SMEM_GEMM>>>(apk + 1L * AP_ELE, hi1, lo1, buf, b21, 3, 1,
                                     nullptr, nullptr, nullptr, nullptr, nullptr);
    gemm_tc<<<gg, NTHR, SMEM_GEMM>>>(apk + 2L * AP_ELE, hi1, lo1, buf, b22, 2, 2,
                                     nullptr, nullptr, nullptr, nullptr, nullptr);
    gemm_tc<<<gg, NTHR, SMEM_GEMM>>>(apk + 3L * AP_ELE, hi1, lo1, buf, b23, 4, 3,
                                     acc2, hi2, lo2, nullptr, nullptr);
    finalize_stats<<<1, 32>>>(acc2, st2);
    // 4) final conv on raw set-2 planes; GN2 folded via rstd scale + rowsum correction
    gemm_tc<<<gg, NTHR, SMEM_GEMM>>>(apk + 4L * AP_ELE, hi2, lo2, out, cvec, -1, 4,
                                     nullptr, nullptr, nullptr, st2, wrs);
}

// round 17
// speedup vs baseline: 1.3697x; 1.3697x over previous
#include <cuda_runtime.h>
#include <cuda_fp16.h>
#include <math.h>
#include <stdint.h>

#define CH 384
#define RR 32
#define S 32768             // 32^3
#define P 34
#define PP 1156             // 34^2
#define SPP 39304           // 34^3
#define BATCH 2
#define KPRIME 768          // 2*384 fp16x2 folded K
#define NSTAGE 12           // KPRIME / 64
#define NPIPE 3             // cp.async pipeline depth
#define AP_ELE (CH * KPRIME)
#define NTHR 256            // 8 warps per CTA

// smem geometry (bytes)
#define A_STRIDE 144        // (64+8) fp16 per row
#define B_STRIDE 272        // (128+8) fp16 per row
#define A_BYTES  (128 * A_STRIDE)   // 18432
#define B_BYTES  (64 * B_STRIDE)    // 17408
#define STAGE_BYTES (A_BYTES + B_BYTES)  // 35840
#define SMEM_GEMM (NPIPE * STAGE_BYTES)  // 107520

// ---------------- scratch (__device__ globals; alloc-free rule) ----------------
__device__ __align__(16) float    g_buf[BATCH * CH * S];            // fp32 activations
__device__ __align__(16) unsigned short g_hi1[BATCH * CH * S];      // dense planes (x, later gn2 input)
__device__ __align__(16) unsigned short g_lo1[BATCH * CH * S];
__device__ __align__(16) unsigned short g_phi[BATCH * CH * SPP];    // padded hi plane (gelu(gn1))
__device__ __align__(16) unsigned short g_plo[BATCH * CH * SPP];    // padded lo plane
__device__ __align__(16) unsigned short g_apack[5 * AP_ELE];        // packed fp16x2 weights
__device__ float g_acc1[2 * BATCH];     // GN1 (sum, sumsq) atomics
__device__ float g_acc2[2 * BATCH];     // GN2 (sum, sumsq) atomics
__device__ float g_stats1[2 * BATCH];   // GN1 (mean, rstd)
__device__ float g_stats2[2 * BATCH];   // GN2 (mean, rstd)
__device__ float g_cvec[CH];            // b3 + w3·bt2
__device__ float g_wrsum[CH];           // rowsum(w3·g2)

__device__ __forceinline__ float gelu_f(float x) {
    return 0.5f * x * (1.0f + erff(x * 0.70710678118654752f));
}

// ---------------- PTX helpers (compute_80-compatible) ----------------
__device__ __forceinline__ uint32_t smem_u32(const void* p) {
    uint32_t a;
    asm("{ .reg .u64 t; cvta.to.shared.u64 t, %1; cvt.u32.u64 %0, t; }" : "=r"(a) : "l"(p));
    return a;
}
__device__ __forceinline__ void cp16(uint32_t dst, const void* src) {
    asm volatile("cp.async.cg.shared.global [%0], [%1], 16;" :: "r"(dst), "l"(src));
}
__device__ __forceinline__ void ldsm4(uint32_t* r, uint32_t addr) {
    asm volatile("ldmatrix.sync.aligned.m8n8.x4.shared.b16 {%0,%1,%2,%3}, [%4];"
        : "=r"(r[0]), "=r"(r[1]), "=r"(r[2]), "=r"(r[3]) : "r"(addr));
}
__device__ __forceinline__ void ldsm4t(uint32_t* r, uint32_t addr) {
    asm volatile("ldmatrix.sync.aligned.m8n8.x4.trans.shared.b16 {%0,%1,%2,%3}, [%4];"
        : "=r"(r[0]), "=r"(r[1]), "=r"(r[2]), "=r"(r[3]) : "r"(addr));
}
__device__ __forceinline__ void mma16816(float* c, const uint32_t* a, uint32_t b0, uint32_t b1) {
    asm volatile("mma.sync.aligned.m16n8k16.row.col.f32.f16.f16.f32 "
        "{%0,%1,%2,%3}, {%4,%5,%6,%7}, {%8,%9}, {%0,%1,%2,%3};"
        : "+f"(c[0]), "+f"(c[1]), "+f"(c[2]), "+f"(c[3])
        : "r"(a[0]), "r"(a[1]), "r"(a[2]), "r"(a[3]), "r"(b0), "r"(b1));
}
// fp16 hi/lo split: v = hi + lo + O(2^-24 v)
__device__ __forceinline__ void split_one(float v, unsigned short& hi, unsigned short& lo) {
    const __half h = __float2half_rn(v);
    const __half l = __float2half_rn(v - __half2float(h));
    hi = __half_as_ushort(h);
    lo = __half_as_ushort(l);
}

// =====================================================================
// HMMA fp16x2 GEMM, 8 warps x (64x32) warp tiles. modes:
//  0: write fp32 acc+bias; fused GN1 stats -> accOut
//  1: write gelu(acc+bias) fp32
//  2: Out += gelu(acc+bias) fp32
//  3: v = Out + gelu(acc+bias); fused GN2 stats -> accOut; write hi/lo planes
//  4: final: v = rstd*acc + (bias[m] - rstd*mean*wrsum[m]); write fp32 Out
// axis: <0 dense planes [b][ch][S]; 2/3/4 = padded planes [b][ch][SPP] + shift
// =====================================================================
__device__ __forceinline__ void load_stage(
    char* smem, uint32_t sb, int c, int tid, int b, int m0, int n0, int axis,
    const unsigned short* __restrict__ apack,
    const unsigned short* __restrict__ hiP,
    const unsigned short* __restrict__ loP)
{
    const uint32_t stOff = (uint32_t)(c % NPIPE) * STAGE_BYTES;
    const uint32_t aBase = sb + stOff;
    const uint32_t bBase = aBase + A_BYTES;
    // ---- A: 128 rows x 64 fp16 (cp.async 16B) ----
    const unsigned short* ag = apack + (long)m0 * KPRIME + c * 64;
    #pragma unroll
    for (int it = 0; it < 4; it++) {
        const int flat = it * NTHR + tid;   // 0..1023
        const int m = flat >> 3, g = flat & 7;
        cp16(aBase + m * A_STRIDE + g * 16, ag + (long)m * KPRIME + g * 8);
    }
    const int kbase = (c % 6) * 64;
    const unsigned short* plane = (c < 6) ? hiP : loP;
    if (axis < 0) {
        // ---- dense B: 64 rows x 16 cp16 ----
        #pragma unroll
        for (int it = 0; it < 4; it++) {
            const int flat = it * NTHR + tid;   // 0..1023
            const int k = flat >> 4, g = flat & 15;
            cp16(bBase + k * B_STRIDE + g * 16,
                 plane + ((long)b * CH + kbase + k) * (long)S + n0 + g * 8);
        }
    } else {
        // ---- shifted B from zero-padded 34^3 planes (branch-free) ----
        #pragma unroll
        for (int it = 0; it < 16; it++) {
            const int flat = it * NTHR + tid;   // 0..4095
            const int k = flat >> 6, ni2 = flat & 63;
            const int ch = kbase + k;
            const int n = n0 + 2 * ni2;
            const int d = n >> 10, h = (n >> 5) & 31, w = n & 31;
            const int sh = 2 - (ch >> 7);       // chunk 0/1/2 -> offset 2/1/0
            int od = 1, oh = 1, ow = 1;
            if      (axis == 2) od = sh;
            else if (axis == 3) oh = sh;
            else                ow = sh;
            const unsigned short* src = plane + ((long)b * CH + ch) * (long)SPP
                        + (d + od) * PP + (h + oh) * P + (w + ow);
            const uint32_t v = (uint32_t)src[0] | ((uint32_t)src[1] << 16);
            *reinterpret_cast<uint32_t*>(smem + stOff + A_BYTES + k * B_STRIDE + ni2 * 4) = v;
        }
    }
    asm volatile("cp.async.commit_group;" ::: "memory");
}

__global__ __launch_bounds__(NTHR, 2)
void gemm_tc(const unsigned short* __restrict__ apack,
             const unsigned short* __restrict__ hiP,
             const unsigned short* __restrict__ loP,
             float* __restrict__ Out, const float* __restrict__ bias,
             int axis, int mode,
             float* __restrict__ accOut,
             unsigned short* __restrict__ outHi, unsigned short* __restrict__ outLo,
             const float* __restrict__ stats2, const float* __restrict__ wrsum)
{
    extern __shared__ char smem[];
    const uint32_t sb = smem_u32(smem);
    const int tid = threadIdx.x, wid = tid >> 5, lane = tid & 31;
    const int m0 = blockIdx.x * 128;
    const int n0 = blockIdx.y * 128;
    const int b  = blockIdx.z;
    const int wm = (wid & 1) * 64;
    const int wn = (wid >> 1) * 32;

    float acc[4][4][4];
    #pragma unroll
    for (int i = 0; i < 4; i++)
        #pragma unroll
        for (int j = 0; j < 4; j++)
            #pragma unroll
            for (int k = 0; k < 4; k++) acc[i][j][k] = 0.f;

    load_stage(smem, sb, 0, tid, b, m0, n0, axis, apack, hiP, loP);
    load_stage(smem, sb, 1, tid, b, m0, n0, axis, apack, hiP, loP);

    for (int c = 0; c < NSTAGE; c++) {
        if (c < NSTAGE - 1)
            asm volatile("cp.async.wait_group 1;" ::: "memory");
        else
            asm volatile("cp.async.wait_group 0;" ::: "memory");
        __syncthreads();

        // prefetch stage c+2 (slot (c+2)%3 == (c-1)%3, free after barrier)
        if (c + 2 < NSTAGE)
            load_stage(smem, sb, c + 2, tid, b, m0, n0, axis, apack, hiP, loP);

        const uint32_t aBase = sb + (uint32_t)(c % NPIPE) * STAGE_BYTES;
        const uint32_t bBase = aBase + A_BYTES;
        #pragma unroll
        for (int ks = 0; ks < 4; ks++) {
            const int k0 = ks * 16;
            uint32_t afr[4][4], bfr[2][4];
            #pragma unroll
            for (int mt = 0; mt < 4; mt++)
                ldsm4(afr[mt], aBase + (wm + mt * 16 + (lane & 15)) * A_STRIDE
                               + (k0 + (lane >> 4) * 8) * 2);
            #pragma unroll
            for (int nt = 0; nt < 2; nt++)
                ldsm4t(bfr[nt], bBase + (k0 + (lane & 15)) * B_STRIDE
                                + (wn + nt * 16 + (lane >> 4) * 8) * 2);
            #pragma unroll
            for (int mt = 0; mt < 4; mt++)
                #pragma unroll
                for (int n8 = 0; n8 < 4; n8++)
                    mma16816(acc[mt][n8], afr[mt],
                             bfr[n8 >> 1][(n8 & 1) * 2],
                             bfr[n8 >> 1][(n8 & 1) * 2 + 1]);
        }
    }

    // ---- epilogue ----
    float mean = 0.f, rstd = 1.f;
    if (mode == 4) { mean = stats2[2 * b]; rstd = stats2[2 * b + 1]; }
    float ls = 0.f, lss = 0.f;
    const int g = lane >> 2, t = lane & 3;
    #pragma unroll
    for (int mt = 0; mt < 4; mt++) {
        #pragma unroll
        for (int half = 0; half < 2; half++) {
            const int m = m0 + wm + mt * 16 + g + half * 8;
            const float bv = bias[m];
            float cc = bv;
            if (mode == 4) cc = bv - rstd * mean * wrsum[m];
            const long rowbase = ((long)b * CH + m) * (long)S + n0 + wn;
            float* op = Out + rowbase;
            #pragma unroll
            for (int n8 = 0; n8 < 4; n8++) {
                float2 v;
                if (mode == 4) {
                    v.x = rstd * acc[mt][n8][half * 2]     + cc;
                    v.y = rstd * acc[mt][n8][half * 2 + 1] + cc;
                } else {
                    v.x = acc[mt][n8][half * 2]     + bv;
                    v.y = acc[mt][n8][half * 2 + 1] + bv;
                }
                if (mode == 1 || mode == 2 || mode == 3) {
                    v.x = gelu_f(v.x); v.y = gelu_f(v.y);
                }
                const int nofs = n8 * 8 + 2 * t;
                if (mode == 2 || mode == 3) {
                    float2 o = *reinterpret_cast<const float2*>(op + nofs);
                    v.x += o.x; v.y += o.y;
                }
                if (mode == 0) {
                    ls += v.x + v.y;
                    lss = fmaf(v.x, v.x, lss); lss = fmaf(v.y, v.y, lss);
                }
                if (mode == 3) {
                    ls += v.x + v.y;
                    lss = fmaf(v.x, v.x, lss); lss = fmaf(v.y, v.y, lss);
                    unsigned short hx, lx, hy, ly;
                    split_one(v.x, hx, lx); split_one(v.y, hy, ly);
                    const long u32i = (rowbase + nofs) >> 1;
                    reinterpret_cast<uint32_t*>(outHi)[u32i] = (uint32_t)hx | ((uint32_t)hy << 16);
                    reinterpret_cast<uint32_t*>(outLo)[u32i] = (uint32_t)lx | ((uint32_t)ly << 16);
                } else {
                    *reinterpret_cast<float2*>(op + nofs) = v;
                }
            }
        }
    }
    // ---- fused stats reduction ----
    if (mode == 0 || mode == 3) {
        #pragma unroll
        for (int off = 16; off; off >>= 1) {
            ls  += __shfl_xor_sync(0xFFFFFFFFu, ls,  off);
            lss += __shfl_xor_sync(0xFFFFFFFFu, lss, off);
        }
        float* sred = reinterpret_cast<float*>(smem);
        __syncthreads();
        if (lane == 0) { sred[wid] = ls; sred[8 + wid] = lss; }
        __syncthreads();
        if (tid == 0) {
            float s = 0.f, ss = 0.f;
            #pragma unroll
            for (int i = 0; i < 8; i++) { s += sred[i]; ss += sred[8 + i]; }
            atomicAdd(&accOut[2 * b],     s);
            atomicAdd(&accOut[2 * b + 1], ss);
        }
    }
}

// ============ zero stats accumulators ============
__global__ void zero_acc()
{
    if (threadIdx.x < 2 * BATCH) { g_acc1[threadIdx.x] = 0.f; g_acc2[threadIdx.x] = 0.f; }
}

// ============ finalize stats: (sum,sumsq) -> (mean, rstd) ============
__global__ void finalize_stats(const float* __restrict__ acc, float* __restrict__ stats)
{
    const int b = threadIdx.x;
    if (b >= BATCH) return;
    const float n = (float)CH * (float)S;
    const float mean = acc[2 * b] / n;
    const float var  = acc[2 * b + 1] / n - mean * mean;
    stats[2 * b]     = mean;
    stats[2 * b + 1] = rsqrtf(var + 1e-5f);
}

// ============ pack weights: [mat][m][ hi(384) | lo(384) ] ============
__global__ void apack_prep(const float* __restrict__ w1, const float* __restrict__ w21,
                           const float* __restrict__ w22, const float* __restrict__ w23,
                           const float* __restrict__ w3, const float* __restrict__ g2)
{
    const int idx = blockIdx.x * blockDim.x + threadIdx.x;
    if (idx >= 5 * CH * CH) return;
    const int mat = idx / (CH * CH);
    const int rem = idx % (CH * CH);
    const int m = rem / CH, k = rem % CH;
    const float* W = (mat == 0) ? w1 : (mat == 1) ? w21 : (mat == 2) ? w22
                   : (mat == 3) ? w23 : w3;
    float v = W[m * CH + k];
    if (mat == 4) v *= g2[k];
    unsigned short hi, lo;
    split_one(v, hi, lo);
    const long base = (long)mat * AP_ELE + (long)m * KPRIME;
    g_apack[base + k]      = hi;
    g_apack[base + CH + k] = lo;
}

// ============ convert raw x -> dense planes ============
__global__ void convert_x(const float* __restrict__ x)
{
    const long i = (long)blockIdx.x * blockDim.x + threadIdx.x;
    const long tot2 = (long)BATCH * CH * S / 2;
    if (i >= tot2) return;
    const float2 v = reinterpret_cast<const float2*>(x)[i];
    unsigned short h0, l0, h1, l1;
    split_one(v.x, h0, l0); split_one(v.y, h1, l1);
    reinterpret_cast<uint32_t*>(g_hi1)[i] = (uint32_t)h0 | ((uint32_t)h1 << 16);
    reinterpret_cast<uint32_t*>(g_lo1)[i] = (uint32_t)l0 | ((uint32_t)l1 << 16);
}

// ============ GN1 affine + GELU -> zero-padded 34^3 planes ============
__global__ void pad_split(const float* __restrict__ g1, const float* __restrict__ bt1)
{
    const long i = (long)blockIdx.x * blockDim.x + threadIdx.x;
    if (i >= (long)BATCH * CH * SPP) return;
    const int b  = (int)(i / ((long)CH * SPP));
    const long r = i - (long)b * CH * SPP;
    const int c  = (int)(r / SPP);
    const int sp = (int)(r - (long)c * SPP);
    const int pd = sp / PP;
    const int r2 = sp - pd * PP;
    const int ph = r2 / P;
    const int pw = r2 - ph * P;
    unsigned short hi = 0, lo = 0;
    if (pd >= 1 && pd <= RR && ph >= 1 && ph <= RR && pw >= 1 && pw <= RR) {
        const int s = (pd - 1) * 1024 + (ph - 1) * RR + (pw - 1);
        float y = g_buf[((long)b * CH + c) * S + s];
        y = gelu_f((y - g_stats1[2 * b]) * g_stats1[2 * b + 1] * g1[c] + bt1[c]);
        split_one(y, hi, lo);
    }
    g_phi[i] = hi; g_plo[i] = lo;
}

// ====== cvec[o] = b3[o] + w3[o,:]·bt2 ; wrsum[o] = (w3·g2)[o,:]·1 ======
__global__ void cvec_kernel(const float* __restrict__ w3,
                            const float* __restrict__ bt2,
                            const float* __restrict__ b3,
                            const float* __restrict__ g2)
{
    const int o = blockIdx.x * blockDim.x + threadIdx.x;
    if (o >= CH) return;
    float s = b3[o], ws = 0.f;
    for (int c = 0; c < CH; c++) {
        s  = fmaf(w3[o * CH + c], bt2[c], s);
        ws = fmaf(w3[o * CH + c], g2[c], ws);
    }
    g_cvec[o]  = s;
    g_wrsum[o] = ws;
}

extern "C" void kernel_launch(void* const* d_in, const int* in_sizes, int n_in,
                              void* d_out, int out_size)
{
    const float* x   = (const float*)d_in[0];
    const float* w1  = (const float*)d_in[1];
    const float* b1  = (const float*)d_in[2];
    const float* g1  = (const float*)d_in[3];
    const float* bt1 = (const float*)d_in[4];
    const float* w21 = (const float*)d_in[5];
    const float* b21 = (const float*)d_in[6];
    const float* w22 = (const float*)d_in[7];
    const float* b22 = (const float*)d_in[8];
    const float* w23 = (const float*)d_in[9];
    const float* b23 = (const float*)d_in[10];
    const float* g2  = (const float*)d_in[11];
    const float* bt2 = (const float*)d_in[12];
    const float* w3  = (const float*)d_in[13];
    const float* b3  = (const float*)d_in[14];
    float* out = (float*)d_out;

    float*          buf;   cudaGetSymbolAddress((void**)&buf,   g_buf);
    unsigned short* hi1;   cudaGetSymbolAddress((void**)&hi1,   g_hi1);
    unsigned short* lo1;   cudaGetSymbolAddress((void**)&lo1,   g_lo1);
    unsigned short* phi;   cudaGetSymbolAddress((void**)&phi,   g_phi);
    unsigned short* plo;   cudaGetSymbolAddress((void**)&plo,   g_plo);
    unsigned short* apk;   cudaGetSymbolAddress((void**)&apk,   g_apack);
    float*          cvec;  cudaGetSymbolAddress((void**)&cvec,  g_cvec);
    float*          wrs;   cudaGetSymbolAddress((void**)&wrs,   g_wrsum);
    float*          acc1;  cudaGetSymbolAddress((void**)&acc1,  g_acc1);
    float*          acc2;  cudaGetSymbolAddress((void**)&acc2,  g_acc2);
    float*          st1;   cudaGetSymbolAddress((void**)&st1,   g_stats1);
    float*          st2;   cudaGetSymbolAddress((void**)&st2,   g_stats2);

    cudaFuncSetAttribute(gemm_tc, cudaFuncAttributeMaxDynamicSharedMemorySize, SMEM_GEMM);

    const dim3 gg(3, S / 128, BATCH);   // m fastest -> L2 reuse of B across m-tiles
    const long tot2 = (long)BATCH * CH * S / 2;
    const unsigned ew = (unsigned)((tot2 + 255) / 256);

    // 0) zero accumulators; pack weights; fold biases; convert x
    zero_acc<<<1, 32>>>();
    apack_prep<<<(5 * CH * CH + 255) / 256, 256>>>(w1, w21, w22, w23, w3, g2);
    cvec_kernel<<<2, 192>>>(w3, bt2, b3, g2);
    convert_x<<<ew, 256>>>(x);
    // 1) conv1 (mode 0: + fused GN1 stats), reads dense x planes
    gemm_tc<<<gg, NTHR, SMEM_GEMM>>>(apk + 0L * AP_ELE, hi1, lo1, buf, b1, -1, 0,
                                     acc1, nullptr, nullptr, nullptr, nullptr);
    finalize_stats<<<1, 32>>>(acc1, st1);
    // 2) GN1 affine + GELU -> zero-padded planes
    {
        const long tot = (long)BATCH * CH * SPP;
        pad_split<<<(unsigned)((tot + 255) / 256), 256>>>(g1, bt1);
    }
    // 3) three shifted branch convs; last fuses GN2 stats + dense-plane rewrite
    gemm_tc<<<gg, NTHR, SMEM_GEMM>>>(apk + 1L * AP_ELE, phi, plo, buf, b21, 3, 1,
                                     nullptr, nullptr, nullptr, nullptr, nullptr);
    gemm_tc<<<gg, NTHR, SMEM_GEMM>>>(apk + 2L * AP_ELE, phi, plo, buf, b22, 2, 2,
                                     nullptr, nullptr, nullptr, nullptr, nullptr);
    gemm_tc<<<gg, NTHR, SMEM_GEMM>>>(apk + 3L * AP_ELE, phi, plo, buf, b23, 4, 3,
                                     acc2, hi1, lo1, nullptr, nullptr);
    finalize_stats<<<1, 32>>>(acc2, st2);
    // 4) final conv on dense planes; GN2 folded via rstd scale + rowsum correction
    gemm_tc<<<gg, NTHR, SMEM_GEMM>>>(apk + 4L * AP_ELE, hi1, lo1, out, cvec, -1, 4,
                                     nullptr, nullptr, nullptr, st2, wrs);
}